// round 11
// baseline (speedup 1.0000x reference)
#include <cuda_runtime.h>
#include <cuda_bf16.h>
#include <math.h>

// ---------------- problem constants ----------------
#define Bn    4
#define Ln    1024
#define DIMn  256
#define HEADSn 8
#define DHn   64
#define DEPTHn 2
#define MLPn  512
#define INNERn 512
#define QKV3n 1536
#define ROWS  (Bn*Ln)     // 4096
#define LP    1032        // padded length (idx 0 = l=-1, idx 1..1024 = l, pad tail)

// ---------------- scratch (device globals; no allocs allowed) ----------------
__device__ float g_c1p[Bn*512*LP];
__device__ float g_c2p[Bn*256*LP];
__device__ float g_w2t[256*1536];
__device__ float g_w3t[256*768];
__device__ float g_x [ROWS*DIMn];
__device__ float g_qkv[ROWS*QKV3n];
__device__ float g_att[ROWS*INNERn];
__device__ float g_mlp[ROWS*MLPn];
__device__ float g_m [ROWS];
__device__ float g_r [ROWS];
__device__ float g_pw[ROWS];
__device__ float g_t [Bn*128];
__device__ float g_u [Bn*Ln];

// ---------------- helpers: tf32 mma ----------------
__device__ __forceinline__ unsigned tf32_of(float f) {
    unsigned u; asm("cvt.rna.tf32.f32 %0, %1;" : "=r"(u) : "f"(f)); return u;
}
__device__ __forceinline__ void mma_tf32(float* c, const unsigned* a, const unsigned* b) {
    asm volatile("mma.sync.aligned.m16n8k8.row.col.f32.tf32.tf32.f32 "
        "{%0,%1,%2,%3}, {%4,%5,%6,%7}, {%8,%9}, {%0,%1,%2,%3};"
        : "+f"(c[0]), "+f"(c[1]), "+f"(c[2]), "+f"(c[3])
        : "r"(a[0]), "r"(a[1]), "r"(a[2]), "r"(a[3]), "r"(b[0]), "r"(b[1]));
}

// ---------------- conv1: 1->256, kernel (1,3), pad (0,1); writes padded ----------------
__global__ void conv1_kernel(const float* __restrict__ img, const float* __restrict__ w,
                             const float* __restrict__ bias, float* __restrict__ out)
{
    int idx = blockIdx.x * 256 + threadIdx.x;
    if (idx >= Bn*256*2*Ln) return;
    int l  = idx & (Ln-1);
    int hh = (idx >> 10) & 1;
    int c  = (idx >> 11) & 255;
    int b  = idx >> 19;
    const float* ir = img + ((size_t)b*2 + hh)*Ln;
    float acc = bias[c];
    #pragma unroll
    for (int k = 0; k < 3; k++) {
        int ll = l + k - 1;
        if (ll >= 0 && ll < Ln) acc += ir[ll] * w[c*3 + k];
    }
    out[((size_t)(b*512 + c*2 + hh))*LP + 1 + l] = fmaxf(acc, 0.f);
}

__global__ void pad_zero_kernel(float* __restrict__ c1p, float* __restrict__ c2p)
{
    int idx = blockIdx.x * 256 + threadIdx.x;
    if (idx < 2048*8) {
        int row = idx >> 3, p = idx & 7;
        int pos = (p == 0) ? 0 : 1024 + p;
        c1p[(size_t)row*LP + pos] = 0.f;
    } else if (idx < 2048*8 + 1024*8) {
        int i2 = idx - 2048*8;
        int row = i2 >> 3, p = i2 & 7;
        int pos = (p == 0) ? 0 : 1024 + p;
        c2p[(size_t)row*LP + pos] = 0.f;
    }
}

__global__ void wtrans_kernel(const float* __restrict__ w, float* __restrict__ wt,
                              int CIN, int total)
{
    int idx = blockIdx.x * 256 + threadIdx.x;
    if (idx >= total) return;
    int K = CIN * 3;
    int co = idx / K, rem = idx - co*K;
    int ch = rem / 3, kk = rem - ch*3;
    wt[(size_t)co*K + kk*CIN + ch] = w[idx];
}

// ---------------- conv as GEMM (2xtf32), software-pipelined ----------------
template<bool TRANSOUT>
__global__ __launch_bounds__(256)
void conv_gemm_kernel(const float* __restrict__ A, const float* __restrict__ inb,
                      const float* __restrict__ bias, float* __restrict__ Cout,
                      int K, int CIN, int cinlog)
{
    constexpr int BM = 64;
    constexpr int NT = 4;
    constexpr int BUFU = 2*BM*36 + 32*132;
    extern __shared__ unsigned smu[];

    int tid = threadIdx.x;
    int warp = tid >> 5, lane = tid & 31;
    int g = lane >> 2, t = lane & 3;
    int wm = warp % 2, wn = warp / 2;
    int bm = blockIdx.y * BM, bn = blockIdx.x * 128;
    int b = blockIdx.z;
    const float* base = inb + (size_t)b * CIN * LP;

    float acc[2][NT][4];
    #pragma unroll
    for (int mt = 0; mt < 2; mt++)
        #pragma unroll
        for (int nt = 0; nt < NT; nt++)
            #pragma unroll
            for (int i = 0; i < 4; i++) acc[mt][nt][i] = 0.f;

    float4 pa[2], pb[4];

    auto LDG_TILE = [&](int k0) {
        #pragma unroll
        for (int v = 0; v < 2; v++) {
            int slot = tid + 256*v;
            int r = slot >> 3, c4 = (slot & 7) * 4;
            pa[v] = *(const float4*)&A[(size_t)(bm + r)*K + k0 + c4];
        }
        #pragma unroll
        for (int v = 0; v < 4; v++) {
            int slot = tid + 256*v;
            int kr = slot >> 5, c4 = (slot & 31) * 4;
            int rr = k0 + kr;
            int kk = rr >> cinlog, ch = rr - (kk << cinlog);
            const float* src = base + (size_t)ch*LP + bn + c4 + kk;
            pb[v] = make_float4(src[0], src[1], src[2], src[3]);
        }
    };
    auto STS_TILE = [&](int buf) {
        unsigned* Ah = smu + buf*BUFU;
        unsigned* Al = Ah + BM*36;
        unsigned* Bs = Ah + 2*BM*36;
        #pragma unroll
        for (int v = 0; v < 2; v++) {
            int slot = tid + 256*v;
            int r = slot >> 3, c4 = (slot & 7) * 4;
            float4 av = pa[v];
            unsigned h0 = tf32_of(av.x), h1 = tf32_of(av.y), h2 = tf32_of(av.z), h3 = tf32_of(av.w);
            *(uint4*)&Ah[r*36 + c4] = make_uint4(h0, h1, h2, h3);
            *(uint4*)&Al[r*36 + c4] = make_uint4(
                tf32_of(av.x - __uint_as_float(h0)), tf32_of(av.y - __uint_as_float(h1)),
                tf32_of(av.z - __uint_as_float(h2)), tf32_of(av.w - __uint_as_float(h3)));
        }
        #pragma unroll
        for (int v = 0; v < 4; v++) {
            int slot = tid + 256*v;
            int kr = slot >> 5, c4 = (slot & 31) * 4;
            *(uint4*)&Bs[kr*132 + c4] = make_uint4(tf32_of(pb[v].x), tf32_of(pb[v].y),
                                                   tf32_of(pb[v].z), tf32_of(pb[v].w));
        }
    };

    int nT = K / 32;
    LDG_TILE(0);
    STS_TILE(0);
    int cur = 0;
    for (int tt = 0; tt < nT; tt++) {
        if (tt + 1 < nT) LDG_TILE((tt+1)*32);
        __syncthreads();
        unsigned* Ah = smu + cur*BUFU;
        unsigned* Al = Ah + BM*36;
        unsigned* Bs = Ah + 2*BM*36;
        #pragma unroll
        for (int kk = 0; kk < 4; kk++) {
            int kb = kk * 8;
            unsigned ah[2][4], al[2][4];
            #pragma unroll
            for (int mt = 0; mt < 2; mt++) {
                int m = wm*32 + mt*16;
                ah[mt][0] = Ah[(m + g    )*36 + kb + t    ];
                ah[mt][1] = Ah[(m + g + 8)*36 + kb + t    ];
                ah[mt][2] = Ah[(m + g    )*36 + kb + t + 4];
                ah[mt][3] = Ah[(m + g + 8)*36 + kb + t + 4];
                al[mt][0] = Al[(m + g    )*36 + kb + t    ];
                al[mt][1] = Al[(m + g + 8)*36 + kb + t    ];
                al[mt][2] = Al[(m + g    )*36 + kb + t + 4];
                al[mt][3] = Al[(m + g + 8)*36 + kb + t + 4];
            }
            #pragma unroll
            for (int nt = 0; nt < NT; nt++) {
                int n = wn*32 + nt*8 + g;
                unsigned bh[2];
                bh[0] = Bs[(kb + t    )*132 + n];
                bh[1] = Bs[(kb + t + 4)*132 + n];
                #pragma unroll
                for (int mt = 0; mt < 2; mt++) {
                    mma_tf32(acc[mt][nt], al[mt], bh);
                    mma_tf32(acc[mt][nt], ah[mt], bh);
                }
            }
        }
        if (tt + 1 < nT) STS_TILE(cur ^ 1);
        cur ^= 1;
    }
    #pragma unroll
    for (int mt = 0; mt < 2; mt++) {
        int r0 = bm + wm*32 + mt*16 + g;
        float b0 = bias[r0], b1 = bias[r0 + 8];
        #pragma unroll
        for (int nt = 0; nt < NT; nt++) {
            int col = bn + wn*32 + nt*8 + 2*t;
            float v00 = fmaxf(acc[mt][nt][0] + b0, 0.f);
            float v01 = fmaxf(acc[mt][nt][1] + b0, 0.f);
            float v10 = fmaxf(acc[mt][nt][2] + b1, 0.f);
            float v11 = fmaxf(acc[mt][nt][3] + b1, 0.f);
            if (TRANSOUT) {
                Cout[((size_t)b*Ln + col    )*DIMn + r0    ] = v00;
                Cout[((size_t)b*Ln + col + 1)*DIMn + r0    ] = v01;
                Cout[((size_t)b*Ln + col    )*DIMn + r0 + 8] = v10;
                Cout[((size_t)b*Ln + col + 1)*DIMn + r0 + 8] = v11;
            } else {
                Cout[((size_t)b*256 + r0    )*LP + 1 + col    ] = v00;
                Cout[((size_t)b*256 + r0    )*LP + 1 + col + 1] = v01;
                Cout[((size_t)b*256 + r0 + 8)*LP + 1 + col    ] = v10;
                Cout[((size_t)b*256 + r0 + 8)*LP + 1 + col + 1] = v11;
            }
        }
    }
}

// ---------------- row stats / mean pool: warp per row ----------------
__global__ void rowstat_kernel(const float* __restrict__ x, float* __restrict__ mean,
                               float* __restrict__ rstd)
{
    int row = blockIdx.x*8 + (threadIdx.x >> 5);
    int lane = threadIdx.x & 31;
    const float* xr = x + (size_t)row*DIMn + lane*8;
    float4 a = *(const float4*)xr;
    float4 c = *(const float4*)(xr + 4);
    float sum = a.x+a.y+a.z+a.w + c.x+c.y+c.z+c.w;
    #pragma unroll
    for (int off = 16; off > 0; off >>= 1) sum += __shfl_xor_sync(0xffffffffu, sum, off);
    float m = sum * (1.f/DIMn);
    float d0=a.x-m, d1=a.y-m, d2=a.z-m, d3=a.w-m;
    float d4=c.x-m, d5=c.y-m, d6=c.z-m, d7=c.w-m;
    float sq = d0*d0+d1*d1+d2*d2+d3*d3+d4*d4+d5*d5+d6*d6+d7*d7;
    #pragma unroll
    for (int off = 16; off > 0; off >>= 1) sq += __shfl_xor_sync(0xffffffffu, sq, off);
    if (lane == 0) {
        mean[row] = m;
        rstd[row] = rsqrtf(sq * (1.f/DIMn) + 1e-5f);
    }
}

__global__ void meanpool_kernel(const float* __restrict__ x, float* __restrict__ w)
{
    int row = blockIdx.x*8 + (threadIdx.x >> 5);
    int lane = threadIdx.x & 31;
    const float* xr = x + (size_t)row*DIMn + lane*8;
    float4 a = *(const float4*)xr;
    float4 c = *(const float4*)(xr + 4);
    float sum = a.x+a.y+a.z+a.w + c.x+c.y+c.z+c.w;
    #pragma unroll
    for (int off = 16; off > 0; off >>= 1) sum += __shfl_xor_sync(0xffffffffu, sum, off);
    if (lane == 0) w[row] = sum * (1.f/DIMn);
}

// ---------------- 2xtf32 GEMM, software-pipelined, optional fused layernorm on A --------
template<int BM, bool GELU, bool HASB, bool HASR, bool LNA>
__global__ __launch_bounds__(256)
void gemm_tf32_kernel(const float* __restrict__ A, const float* __restrict__ Bm,
                      const float* __restrict__ bias, const float* __restrict__ resid,
                      float* __restrict__ C, int M, int N, int K,
                      const float* __restrict__ lnm, const float* __restrict__ lnr,
                      const float* __restrict__ lns, const float* __restrict__ lnb)
{
    constexpr int WM  = BM/32;
    constexpr int WN  = 8/WM;
    constexpr int WTN = 128/WN;
    constexpr int NT  = WTN/8;
    constexpr int AV  = BM/32;
    constexpr int BUFU = 2*BM*36 + 32*132;
    extern __shared__ unsigned smu[];

    int tid = threadIdx.x;
    int warp = tid >> 5, lane = tid & 31;
    int g = lane >> 2, t = lane & 3;
    int wm = warp % WM, wn = warp / WM;
    int bm = blockIdx.y * BM, bn = blockIdx.x * 128;

    float acc[2][NT][4];
    #pragma unroll
    for (int mt = 0; mt < 2; mt++)
        #pragma unroll
        for (int nt = 0; nt < NT; nt++)
            #pragma unroll
            for (int i = 0; i < 4; i++) acc[mt][nt][i] = 0.f;

    float4 pa[AV], pb[4];
    float pm[AV], pr[AV];

    if (LNA) {
        #pragma unroll
        for (int v = 0; v < AV; v++) {
            int slot = tid + 256*v;
            int r = slot >> 3;
            pm[v] = lnm[bm + r];
            pr[v] = lnr[bm + r];
        }
    }

    auto LDG_TILE = [&](int k0) {
        #pragma unroll
        for (int v = 0; v < AV; v++) {
            int slot = tid + 256*v;
            int r = slot >> 3, c4 = (slot & 7) * 4;
            pa[v] = *(const float4*)&A[(size_t)(bm + r)*K + k0 + c4];
        }
        #pragma unroll
        for (int v = 0; v < 4; v++) {
            int slot = tid + 256*v;
            int kr = slot >> 5, c4 = (slot & 31) * 4;
            pb[v] = *(const float4*)&Bm[(size_t)(k0 + kr)*N + bn + c4];
        }
    };
    auto STS_TILE = [&](int buf, int k0) {
        unsigned* Ah = smu + buf*BUFU;
        unsigned* Al = Ah + BM*36;
        unsigned* Bs = Ah + 2*BM*36;
        #pragma unroll
        for (int v = 0; v < AV; v++) {
            int slot = tid + 256*v;
            int r = slot >> 3, c4 = (slot & 7) * 4;
            float4 av = pa[v];
            if (LNA) {
                float4 s4 = *(const float4*)&lns[k0 + c4];
                float4 b4 = *(const float4*)&lnb[k0 + c4];
                float mm = pm[v], rs = pr[v];
                av.x = (av.x - mm)*rs*s4.x + b4.x;
                av.y = (av.y - mm)*rs*s4.y + b4.y;
                av.z = (av.z - mm)*rs*s4.z + b4.z;
                av.w = (av.w - mm)*rs*s4.w + b4.w;
            }
            unsigned h0 = tf32_of(av.x), h1 = tf32_of(av.y), h2 = tf32_of(av.z), h3 = tf32_of(av.w);
            *(uint4*)&Ah[r*36 + c4] = make_uint4(h0, h1, h2, h3);
            *(uint4*)&Al[r*36 + c4] = make_uint4(
                tf32_of(av.x - __uint_as_float(h0)), tf32_of(av.y - __uint_as_float(h1)),
                tf32_of(av.z - __uint_as_float(h2)), tf32_of(av.w - __uint_as_float(h3)));
        }
        #pragma unroll
        for (int v = 0; v < 4; v++) {
            int slot = tid + 256*v;
            int kr = slot >> 5, c4 = (slot & 31) * 4;
            *(uint4*)&Bs[kr*132 + c4] = make_uint4(tf32_of(pb[v].x), tf32_of(pb[v].y),
                                                   tf32_of(pb[v].z), tf32_of(pb[v].w));
        }
    };

    int nT = K / 32;
    LDG_TILE(0);
    STS_TILE(0, 0);
    int cur = 0;
    for (int tt = 0; tt < nT; tt++) {
        if (tt + 1 < nT) LDG_TILE((tt+1)*32);
        __syncthreads();
        unsigned* Ah = smu + cur*BUFU;
        unsigned* Al = Ah + BM*36;
        unsigned* Bs = Ah + 2*BM*36;
        #pragma unroll
        for (int kk = 0; kk < 4; kk++) {
            int kb = kk * 8;
            unsigned ah[2][4], al[2][4];
            #pragma unroll
            for (int mt = 0; mt < 2; mt++) {
                int m = wm*32 + mt*16;
                ah[mt][0] = Ah[(m + g    )*36 + kb + t    ];
                ah[mt][1] = Ah[(m + g + 8)*36 + kb + t    ];
                ah[mt][2] = Ah[(m + g    )*36 + kb + t + 4];
                ah[mt][3] = Ah[(m + g + 8)*36 + kb + t + 4];
                al[mt][0] = Al[(m + g    )*36 + kb + t    ];
                al[mt][1] = Al[(m + g + 8)*36 + kb + t    ];
                al[mt][2] = Al[(m + g    )*36 + kb + t + 4];
                al[mt][3] = Al[(m + g + 8)*36 + kb + t + 4];
            }
            #pragma unroll
            for (int nt = 0; nt < NT; nt++) {
                int n = wn*WTN + nt*8 + g;
                unsigned bh[2];
                bh[0] = Bs[(kb + t    )*132 + n];
                bh[1] = Bs[(kb + t + 4)*132 + n];
                #pragma unroll
                for (int mt = 0; mt < 2; mt++) {
                    mma_tf32(acc[mt][nt], al[mt], bh);   // lo*hi
                    mma_tf32(acc[mt][nt], ah[mt], bh);   // hi*hi
                }
            }
        }
        if (tt + 1 < nT) STS_TILE(cur ^ 1, (tt+1)*32);
        cur ^= 1;
    }
    #pragma unroll
    for (int mt = 0; mt < 2; mt++) {
        int r0 = bm + wm*32 + mt*16 + g;
        #pragma unroll
        for (int nt = 0; nt < NT; nt++) {
            int col = bn + wn*WTN + nt*8 + 2*t;
            float2 v0 = make_float2(acc[mt][nt][0], acc[mt][nt][1]);
            float2 v1 = make_float2(acc[mt][nt][2], acc[mt][nt][3]);
            if (HASB) {
                float2 bb = *(const float2*)&bias[col];
                v0.x += bb.x; v0.y += bb.y; v1.x += bb.x; v1.y += bb.y;
            }
            if (GELU) {
                v0.x = 0.5f*v0.x*(1.f + erff(v0.x*0.70710678118f));
                v0.y = 0.5f*v0.y*(1.f + erff(v0.y*0.70710678118f));
                v1.x = 0.5f*v1.x*(1.f + erff(v1.x*0.70710678118f));
                v1.y = 0.5f*v1.y*(1.f + erff(v1.y*0.70710678118f));
            }
            if (HASR) {
                float2 r0v = *(const float2*)&resid[(size_t)r0*N + col];
                float2 r1v = *(const float2*)&resid[(size_t)(r0+8)*N + col];
                v0.x += r0v.x; v0.y += r0v.y; v1.x += r1v.x; v1.y += r1v.y;
            }
            *(float2*)&C[(size_t)r0*N + col]     = v0;
            *(float2*)&C[(size_t)(r0+8)*N + col] = v1;
        }
    }
}

// ---------------- flash attention (tf32 mma), 128 q-rows / 256 threads ----------------
__global__ __launch_bounds__(256, 2)
void attn_kernel(const float* __restrict__ qkv, const float* __restrict__ pos,
                 float* __restrict__ out)
{
    extern __shared__ unsigned smu[];
    unsigned* Qs = smu;                 // [128][68]
    unsigned* Ks = smu + 128*68;        // [64][68]  (j-major)
    unsigned* Vs = smu + 192*68;        // [64][68]
    unsigned* Ps = smu + 256*68;        // [128][68]

    int bq = blockIdx.x, h = blockIdx.y, b = blockIdx.z;
    int i0 = bq * 128;
    int tid = threadIdx.x;
    int warp = tid >> 5, lane = tid & 31;
    int g = lane >> 2, t = lane & 3;
    int m0 = warp * 16;
    const float* base = qkv + (size_t)b * Ln * QKV3n;

    #pragma unroll
    for (int v = 0; v < 8; v++) {
        int f = tid + 256*v;
        int r = f >> 4, c4 = (f & 15) * 4;
        float4 qv = *(const float4*)&base[(size_t)(i0 + r)*QKV3n + h*64 + c4];
        *(uint4*)&Qs[r*68 + c4] = make_uint4(tf32_of(qv.x), tf32_of(qv.y), tf32_of(qv.z), tf32_of(qv.w));
    }

    float o[8][4];
    #pragma unroll
    for (int nt = 0; nt < 8; nt++)
        #pragma unroll
        for (int i = 0; i < 4; i++) o[nt][i] = 0.f;
    float mrow0 = -1e30f, mrow1 = -1e30f, lrow0 = 0.f, lrow1 = 0.f;

    const float* pr0 = pos + ((size_t)(h*Ln + i0 + m0 + g    ))*Ln;
    const float* pr1 = pos + ((size_t)(h*Ln + i0 + m0 + g + 8))*Ln;

    for (int jt = 0; jt < 16; jt++) {
        int j0 = jt * 64;
        __syncthreads();
        #pragma unroll
        for (int v = 0; v < 4; v++) {
            int f = tid + 256*v;
            int r = f >> 4, c4 = (f & 15) * 4;
            float4 kv = *(const float4*)&base[(size_t)(j0 + r)*QKV3n + INNERn + h*64 + c4];
            *(uint4*)&Ks[r*68 + c4] = make_uint4(tf32_of(kv.x), tf32_of(kv.y), tf32_of(kv.z), tf32_of(kv.w));
            float4 vv = *(const float4*)&base[(size_t)(j0 + r)*QKV3n + 2*INNERn + h*64 + c4];
            *(uint4*)&Vs[r*68 + c4] = make_uint4(tf32_of(vv.x), tf32_of(vv.y), tf32_of(vv.z), tf32_of(vv.w));
        }
        __syncthreads();

        float sa[8][4];
        #pragma unroll
        for (int nt = 0; nt < 8; nt++)
            #pragma unroll
            for (int i = 0; i < 4; i++) sa[nt][i] = 0.f;
        #pragma unroll
        for (int kc = 0; kc < 8; kc++) {
            int kb = kc * 8;
            unsigned a[4];
            a[0] = Qs[(m0 + g    )*68 + kb + t    ];
            a[1] = Qs[(m0 + g + 8)*68 + kb + t    ];
            a[2] = Qs[(m0 + g    )*68 + kb + t + 4];
            a[3] = Qs[(m0 + g + 8)*68 + kb + t + 4];
            #pragma unroll
            for (int nt = 0; nt < 8; nt++) {
                int n = nt*8 + g;
                unsigned bb[2];
                bb[0] = Ks[n*68 + kb + t    ];
                bb[1] = Ks[n*68 + kb + t + 4];
                mma_tf32(sa[nt], a, bb);
            }
        }
        #pragma unroll
        for (int nt = 0; nt < 8; nt++) {
            float2 p0 = *(const float2*)&pr0[j0 + nt*8 + 2*t];
            float2 p1 = *(const float2*)&pr1[j0 + nt*8 + 2*t];
            sa[nt][0] = sa[nt][0]*0.125f + p0.x;
            sa[nt][1] = sa[nt][1]*0.125f + p0.y;
            sa[nt][2] = sa[nt][2]*0.125f + p1.x;
            sa[nt][3] = sa[nt][3]*0.125f + p1.y;
        }
        float mx0 = -1e30f, mx1 = -1e30f;
        #pragma unroll
        for (int nt = 0; nt < 8; nt++) {
            mx0 = fmaxf(mx0, fmaxf(sa[nt][0], sa[nt][1]));
            mx1 = fmaxf(mx1, fmaxf(sa[nt][2], sa[nt][3]));
        }
        mx0 = fmaxf(mx0, __shfl_xor_sync(0xffffffffu, mx0, 1));
        mx0 = fmaxf(mx0, __shfl_xor_sync(0xffffffffu, mx0, 2));
        mx1 = fmaxf(mx1, __shfl_xor_sync(0xffffffffu, mx1, 1));
        mx1 = fmaxf(mx1, __shfl_xor_sync(0xffffffffu, mx1, 2));
        float mn0 = fmaxf(mrow0, mx0), mn1 = fmaxf(mrow1, mx1);
        float corr0 = __expf(mrow0 - mn0), corr1 = __expf(mrow1 - mn1);
        float ts0 = 0.f, ts1 = 0.f;
        #pragma unroll
        for (int nt = 0; nt < 8; nt++) {
            float e0 = __expf(sa[nt][0] - mn0);
            float e1 = __expf(sa[nt][1] - mn0);
            float e2 = __expf(sa[nt][2] - mn1);
            float e3 = __expf(sa[nt][3] - mn1);
            ts0 += e0 + e1; ts1 += e2 + e3;
            int c = nt*8 + 2*t;
            *(uint2*)&Ps[(m0 + g    )*68 + c] = make_uint2(tf32_of(e0), tf32_of(e1));
            *(uint2*)&Ps[(m0 + g + 8)*68 + c] = make_uint2(tf32_of(e2), tf32_of(e3));
        }
        ts0 += __shfl_xor_sync(0xffffffffu, ts0, 1);
        ts0 += __shfl_xor_sync(0xffffffffu, ts0, 2);
        ts1 += __shfl_xor_sync(0xffffffffu, ts1, 1);
        ts1 += __shfl_xor_sync(0xffffffffu, ts1, 2);
        lrow0 = lrow0*corr0 + ts0;
        lrow1 = lrow1*corr1 + ts1;
        mrow0 = mn0; mrow1 = mn1;
        #pragma unroll
        for (int nt = 0; nt < 8; nt++) {
            o[nt][0] *= corr0; o[nt][1] *= corr0;
            o[nt][2] *= corr1; o[nt][3] *= corr1;
        }
        __syncwarp();
        #pragma unroll
        for (int kc = 0; kc < 8; kc++) {
            int kb = kc * 8;
            unsigned a[4];
            a[0] = Ps[(m0 + g    )*68 + kb + t    ];
            a[1] = Ps[(m0 + g + 8)*68 + kb + t    ];
            a[2] = Ps[(m0 + g    )*68 + kb + t + 4];
            a[3] = Ps[(m0 + g + 8)*68 + kb + t + 4];
            #pragma unroll
            for (int nt = 0; nt < 8; nt++) {
                unsigned bb[2];
                bb[0] = Vs[(kb + t    )*68 + nt*8 + g];
                bb[1] = Vs[(kb + t + 4)*68 + nt*8 + g];
                mma_tf32(o[nt], a, bb);
            }
        }
    }
    float inv0 = 1.f / lrow0, inv1 = 1.f / lrow1;
    size_t r0 = (size_t)b*Ln + i0 + m0 + g;
    size_t r1 = r0 + 8;
    #pragma unroll
    for (int nt = 0; nt < 8; nt++) {
        int col = h*64 + nt*8 + 2*t;
        *(float2*)&out[r0*INNERn + col] = make_float2(o[nt][0]*inv0, o[nt][1]*inv0);
        *(float2*)&out[r1*INNERn + col] = make_float2(o[nt][2]*inv1, o[nt][3]*inv1);
    }
}

// ---------------- SE pool tail ----------------
__global__ void se1_kernel(const float* __restrict__ wv, const float* __restrict__ w1,
                           const float* __restrict__ b1, float* __restrict__ t)
{
    int tid = threadIdx.x;                            // 512
    int b = tid >> 7, j = tid & 127;
    float acc = b1[j];
    for (int l = 0; l < Ln; l++) acc += wv[b*Ln + l] * w1[l*128 + j];
    t[tid] = fmaxf(acc, 0.f);
}

__global__ void se2_kernel(const float* __restrict__ t, const float* __restrict__ w2,
                           const float* __restrict__ b2, float* __restrict__ u)
{
    int idx = blockIdx.x * 256 + threadIdx.x;         // 4096
    int b = idx >> 10, l = idx & (Ln-1);
    float acc = b2[l];
    #pragma unroll
    for (int j = 0; j < 128; j++) acc += t[b*128 + j] * w2[j*Ln + l];
    u[idx] = 1.f / (1.f + __expf(-acc));
}

__global__ void pool_out_kernel(const float* __restrict__ u, const float* __restrict__ x,
                                float* __restrict__ out)
{
    int b = blockIdx.x, d = threadIdx.x;              // 4 x 256
    float acc = 0.f;
    for (int l = 0; l < Ln; l++) acc += u[b*Ln + l] * x[((size_t)b*Ln + l)*DIMn + d];
    out[b*DIMn + d] = acc;
}

// ---------------- host launch ----------------
extern "C" void kernel_launch(void* const* d_in, const int* in_sizes, int n_in,
                              void* d_out, int out_size)
{
    const float* img     = (const float*)d_in[0];
    const float* conv1_w = (const float*)d_in[1];
    const float* conv1_b = (const float*)d_in[2];
    const float* conv2_w = (const float*)d_in[3];
    const float* conv2_b = (const float*)d_in[4];
    const float* conv3_w = (const float*)d_in[5];
    const float* conv3_b = (const float*)d_in[6];
    const float* ln1_s   = (const float*)d_in[7];
    const float* ln1_b   = (const float*)d_in[8];
    const float* qkv_w   = (const float*)d_in[9];
    const float* pos     = (const float*)d_in[10];
    const float* out_w   = (const float*)d_in[11];
    const float* out_b   = (const float*)d_in[12];
    const float* ln2_s   = (const float*)d_in[13];
    const float* ln2_b   = (const float*)d_in[14];
    const float* ff_w1   = (const float*)d_in[15];
    const float* ff_b1   = (const float*)d_in[16];
    const float* ff_w2   = (const float*)d_in[17];
    const float* ff_b2   = (const float*)d_in[18];
    const float* se_w1   = (const float*)d_in[19];
    const float* se_b1   = (const float*)d_in[20];
    const float* se_w2   = (const float*)d_in[21];
    const float* se_b2   = (const float*)d_in[22];
    float* out = (float*)d_out;

    float *c1p, *c2p, *w2t, *w3t, *x, *qkv, *att, *mlp, *mstat, *rstat, *pw, *t, *u;
    cudaGetSymbolAddress((void**)&c1p, g_c1p);
    cudaGetSymbolAddress((void**)&c2p, g_c2p);
    cudaGetSymbolAddress((void**)&w2t, g_w2t);
    cudaGetSymbolAddress((void**)&w3t, g_w3t);
    cudaGetSymbolAddress((void**)&x,   g_x);
    cudaGetSymbolAddress((void**)&qkv, g_qkv);
    cudaGetSymbolAddress((void**)&att, g_att);
    cudaGetSymbolAddress((void**)&mlp, g_mlp);
    cudaGetSymbolAddress((void**)&mstat, g_m);
    cudaGetSymbolAddress((void**)&rstat, g_r);
    cudaGetSymbolAddress((void**)&pw,  g_pw);
    cudaGetSymbolAddress((void**)&t,   g_t);
    cudaGetSymbolAddress((void**)&u,   g_u);

    const int ATTN_SMEM = 384 * 68 * 4;                        // 104448 B
    const int GEMM_SMEM_128 = 2*(2*128*36 + 32*132) * 4;       // 107520 B
    const int GEMM_SMEM_64  = 2*(2*64*36  + 32*132) * 4;       // 70656 B
    cudaFuncSetAttribute(attn_kernel, cudaFuncAttributeMaxDynamicSharedMemorySize, ATTN_SMEM);
    cudaFuncSetAttribute(gemm_tf32_kernel<128,false,false,false,true>,
                         cudaFuncAttributeMaxDynamicSharedMemorySize, GEMM_SMEM_128);
    cudaFuncSetAttribute(gemm_tf32_kernel<128,true,true,false,true>,
                         cudaFuncAttributeMaxDynamicSharedMemorySize, GEMM_SMEM_128);
    cudaFuncSetAttribute(gemm_tf32_kernel<64,false,true,true,false>,
                         cudaFuncAttributeMaxDynamicSharedMemorySize, GEMM_SMEM_64);
    cudaFuncSetAttribute(conv_gemm_kernel<false>,
                         cudaFuncAttributeMaxDynamicSharedMemorySize, GEMM_SMEM_64);
    cudaFuncSetAttribute(conv_gemm_kernel<true>,
                         cudaFuncAttributeMaxDynamicSharedMemorySize, GEMM_SMEM_64);

    // conv patch embed
    conv1_kernel<<<(Bn*256*2*Ln + 255)/256, 256>>>(img, conv1_w, conv1_b, c1p);
    pad_zero_kernel<<<(2048*8 + 1024*8 + 255)/256, 256>>>(c1p, c2p);
    wtrans_kernel<<<(256*1536 + 255)/256, 256>>>(conv2_w, w2t, 512, 256*1536);
    wtrans_kernel<<<(256*768  + 255)/256, 256>>>(conv3_w, w3t, 256, 256*768);
    conv_gemm_kernel<false><<<dim3(8, 4, Bn), 256, GEMM_SMEM_64>>>(w2t, c1p, conv2_b, c2p, 1536, 512, 9);
    conv_gemm_kernel<true ><<<dim3(8, 4, Bn), 256, GEMM_SMEM_64>>>(w3t, c2p, conv3_b, x,   768,  256, 8);

    for (int lyr = 0; lyr < DEPTHn; lyr++) {
        // attention block (LN fused into qkv A-staging)
        rowstat_kernel<<<ROWS/8, 256>>>(x, mstat, rstat);
        gemm_tf32_kernel<128,false,false,false,true><<<dim3(QKV3n/128, ROWS/128), 256, GEMM_SMEM_128>>>(
            x, qkv_w + (size_t)lyr*DIMn*QKV3n, nullptr, nullptr, qkv, ROWS, QKV3n, DIMn,
            mstat, rstat, ln1_s + lyr*DIMn, ln1_b + lyr*DIMn);
        attn_kernel<<<dim3(Ln/128, HEADSn, Bn), 256, ATTN_SMEM>>>(
            qkv, pos + (size_t)lyr*HEADSn*Ln*Ln, att);
        gemm_tf32_kernel<64,false,true,true,false><<<dim3(DIMn/128, ROWS/64), 256, GEMM_SMEM_64>>>(
            att, out_w + (size_t)lyr*INNERn*DIMn, out_b + lyr*DIMn, x, x, ROWS, DIMn, INNERn,
            nullptr, nullptr, nullptr, nullptr);
        // MLP block (LN fused into ff1 A-staging)
        rowstat_kernel<<<ROWS/8, 256>>>(x, mstat, rstat);
        gemm_tf32_kernel<128,true,true,false,true><<<dim3(MLPn/128, ROWS/128), 256, GEMM_SMEM_128>>>(
            x, ff_w1 + (size_t)lyr*DIMn*MLPn, ff_b1 + lyr*MLPn, nullptr, mlp, ROWS, MLPn, DIMn,
            mstat, rstat, ln2_s + lyr*DIMn, ln2_b + lyr*DIMn);
        gemm_tf32_kernel<64,false,true,true,false><<<dim3(DIMn/128, ROWS/64), 256, GEMM_SMEM_64>>>(
            mlp, ff_w2 + (size_t)lyr*MLPn*DIMn, ff_b2 + lyr*DIMn, x, x, ROWS, DIMn, MLPn,
            nullptr, nullptr, nullptr, nullptr);
    }

    // SE attention pool
    meanpool_kernel<<<ROWS/8, 256>>>(x, pw);
    se1_kernel<<<1, 512>>>(pw, se_w1, se_b1, t);
    se2_kernel<<<(Bn*Ln)/256, 256>>>(t, se_w2, se_b2, u);
    pool_out_kernel<<<Bn, 256>>>(u, x, out);
}

// round 15
// speedup vs baseline: 1.4249x; 1.4249x over previous
#include <cuda_runtime.h>
#include <cuda_bf16.h>
#include <math.h>

// ---------------- problem constants ----------------
#define Bn    4
#define Ln    1024
#define DIMn  256
#define HEADSn 8
#define DHn   64
#define DEPTHn 2
#define MLPn  512
#define INNERn 512
#define QKV3n 1536
#define ROWS  (Bn*Ln)     // 4096
#define LP    1032        // padded length (idx 0 = l=-1, idx 1..1024 = l, pad tail)

// ---------------- scratch (device globals; no allocs allowed) ----------------
__device__ float g_c1p[Bn*512*LP];
__device__ float g_c2p[Bn*256*LP];
__device__ float g_w2t[256*1536];
__device__ float g_w3t[256*768];
__device__ float g_x [ROWS*DIMn];
__device__ float g_qkv[ROWS*QKV3n];
__device__ float g_att[ROWS*INNERn];
__device__ float g_mlp[ROWS*MLPn];
__device__ float g_m [ROWS];
__device__ float g_r [ROWS];
__device__ float g_pw[ROWS];
__device__ float g_t [Bn*128];
__device__ float g_u [Bn*Ln];

// ---------------- helpers: tf32 mma ----------------
__device__ __forceinline__ unsigned tf32_of(float f) {
    unsigned u; asm("cvt.rna.tf32.f32 %0, %1;" : "=r"(u) : "f"(f)); return u;
}
__device__ __forceinline__ void mma_tf32(float* c, const unsigned* a, const unsigned* b) {
    asm volatile("mma.sync.aligned.m16n8k8.row.col.f32.tf32.tf32.f32 "
        "{%0,%1,%2,%3}, {%4,%5,%6,%7}, {%8,%9}, {%0,%1,%2,%3};"
        : "+f"(c[0]), "+f"(c[1]), "+f"(c[2]), "+f"(c[3])
        : "r"(a[0]), "r"(a[1]), "r"(a[2]), "r"(a[3]), "r"(b[0]), "r"(b[1]));
}

// ---------------- conv1: 1->256, kernel (1,3), pad (0,1); writes padded ----------------
__global__ void conv1_kernel(const float* __restrict__ img, const float* __restrict__ w,
                             const float* __restrict__ bias, float* __restrict__ out)
{
    int idx = blockIdx.x * 256 + threadIdx.x;
    if (idx >= Bn*256*2*Ln) return;
    int l  = idx & (Ln-1);
    int hh = (idx >> 10) & 1;
    int c  = (idx >> 11) & 255;
    int b  = idx >> 19;
    const float* ir = img + ((size_t)b*2 + hh)*Ln;
    float acc = bias[c];
    #pragma unroll
    for (int k = 0; k < 3; k++) {
        int ll = l + k - 1;
        if (ll >= 0 && ll < Ln) acc += ir[ll] * w[c*3 + k];
    }
    out[((size_t)(b*512 + c*2 + hh))*LP + 1 + l] = fmaxf(acc, 0.f);
}

__global__ void pad_zero_kernel(float* __restrict__ c1p, float* __restrict__ c2p)
{
    int idx = blockIdx.x * 256 + threadIdx.x;
    if (idx < 2048*8) {
        int row = idx >> 3, p = idx & 7;
        int pos = (p == 0) ? 0 : 1024 + p;
        c1p[(size_t)row*LP + pos] = 0.f;
    } else if (idx < 2048*8 + 1024*8) {
        int i2 = idx - 2048*8;
        int row = i2 >> 3, p = i2 & 7;
        int pos = (p == 0) ? 0 : 1024 + p;
        c2p[(size_t)row*LP + pos] = 0.f;
    }
}

__global__ void wtrans_kernel(const float* __restrict__ w, float* __restrict__ wt,
                              int CIN, int total)
{
    int idx = blockIdx.x * 256 + threadIdx.x;
    if (idx >= total) return;
    int K = CIN * 3;
    int co = idx / K, rem = idx - co*K;
    int ch = rem / 3, kk = rem - ch*3;
    wt[(size_t)co*K + kk*CIN + ch] = w[idx];
}

// ---------------- conv as GEMM (2xtf32), software-pipelined ----------------
template<bool TRANSOUT>
__global__ __launch_bounds__(256)
void conv_gemm_kernel(const float* __restrict__ A, const float* __restrict__ inb,
                      const float* __restrict__ bias, float* __restrict__ Cout,
                      int K, int CIN, int cinlog)
{
    constexpr int BM = 64;
    constexpr int NT = 4;
    constexpr int BUFU = 2*BM*36 + 32*132;
    extern __shared__ unsigned smu[];

    int tid = threadIdx.x;
    int warp = tid >> 5, lane = tid & 31;
    int g = lane >> 2, t = lane & 3;
    int wm = warp % 2, wn = warp / 2;
    int bm = blockIdx.y * BM, bn = blockIdx.x * 128;
    int b = blockIdx.z;
    const float* base = inb + (size_t)b * CIN * LP;

    float acc[2][NT][4];
    #pragma unroll
    for (int mt = 0; mt < 2; mt++)
        #pragma unroll
        for (int nt = 0; nt < NT; nt++)
            #pragma unroll
            for (int i = 0; i < 4; i++) acc[mt][nt][i] = 0.f;

    float4 pa[2], pb[4];

    auto LDG_TILE = [&](int k0) {
        #pragma unroll
        for (int v = 0; v < 2; v++) {
            int slot = tid + 256*v;
            int r = slot >> 3, c4 = (slot & 7) * 4;
            pa[v] = *(const float4*)&A[(size_t)(bm + r)*K + k0 + c4];
        }
        #pragma unroll
        for (int v = 0; v < 4; v++) {
            int slot = tid + 256*v;
            int kr = slot >> 5, c4 = (slot & 31) * 4;
            int rr = k0 + kr;
            int kk = rr >> cinlog, ch = rr - (kk << cinlog);
            const float* src = base + (size_t)ch*LP + bn + c4 + kk;
            pb[v] = make_float4(src[0], src[1], src[2], src[3]);
        }
    };
    auto STS_TILE = [&](int buf) {
        unsigned* Ah = smu + buf*BUFU;
        unsigned* Al = Ah + BM*36;
        unsigned* Bs = Ah + 2*BM*36;
        #pragma unroll
        for (int v = 0; v < 2; v++) {
            int slot = tid + 256*v;
            int r = slot >> 3, c4 = (slot & 7) * 4;
            float4 av = pa[v];
            unsigned h0 = tf32_of(av.x), h1 = tf32_of(av.y), h2 = tf32_of(av.z), h3 = tf32_of(av.w);
            *(uint4*)&Ah[r*36 + c4] = make_uint4(h0, h1, h2, h3);
            *(uint4*)&Al[r*36 + c4] = make_uint4(
                tf32_of(av.x - __uint_as_float(h0)), tf32_of(av.y - __uint_as_float(h1)),
                tf32_of(av.z - __uint_as_float(h2)), tf32_of(av.w - __uint_as_float(h3)));
        }
        #pragma unroll
        for (int v = 0; v < 4; v++) {
            int slot = tid + 256*v;
            int kr = slot >> 5, c4 = (slot & 31) * 4;
            *(uint4*)&Bs[kr*132 + c4] = make_uint4(tf32_of(pb[v].x), tf32_of(pb[v].y),
                                                   tf32_of(pb[v].z), tf32_of(pb[v].w));
        }
    };

    int nT = K / 32;
    LDG_TILE(0);
    STS_TILE(0);
    int cur = 0;
    for (int tt = 0; tt < nT; tt++) {
        if (tt + 1 < nT) LDG_TILE((tt+1)*32);
        __syncthreads();
        unsigned* Ah = smu + cur*BUFU;
        unsigned* Al = Ah + BM*36;
        unsigned* Bs = Ah + 2*BM*36;
        #pragma unroll
        for (int kk = 0; kk < 4; kk++) {
            int kb = kk * 8;
            unsigned ah[2][4], al[2][4];
            #pragma unroll
            for (int mt = 0; mt < 2; mt++) {
                int m = wm*32 + mt*16;
                ah[mt][0] = Ah[(m + g    )*36 + kb + t    ];
                ah[mt][1] = Ah[(m + g + 8)*36 + kb + t    ];
                ah[mt][2] = Ah[(m + g    )*36 + kb + t + 4];
                ah[mt][3] = Ah[(m + g + 8)*36 + kb + t + 4];
                al[mt][0] = Al[(m + g    )*36 + kb + t    ];
                al[mt][1] = Al[(m + g + 8)*36 + kb + t    ];
                al[mt][2] = Al[(m + g    )*36 + kb + t + 4];
                al[mt][3] = Al[(m + g + 8)*36 + kb + t + 4];
            }
            #pragma unroll
            for (int nt = 0; nt < NT; nt++) {
                int n = wn*32 + nt*8 + g;
                unsigned bh[2];
                bh[0] = Bs[(kb + t    )*132 + n];
                bh[1] = Bs[(kb + t + 4)*132 + n];
                #pragma unroll
                for (int mt = 0; mt < 2; mt++) {
                    mma_tf32(acc[mt][nt], al[mt], bh);
                    mma_tf32(acc[mt][nt], ah[mt], bh);
                }
            }
        }
        if (tt + 1 < nT) STS_TILE(cur ^ 1);
        cur ^= 1;
    }
    #pragma unroll
    for (int mt = 0; mt < 2; mt++) {
        int r0 = bm + wm*32 + mt*16 + g;
        float b0 = bias[r0], b1 = bias[r0 + 8];
        #pragma unroll
        for (int nt = 0; nt < NT; nt++) {
            int col = bn + wn*32 + nt*8 + 2*t;
            float v00 = fmaxf(acc[mt][nt][0] + b0, 0.f);
            float v01 = fmaxf(acc[mt][nt][1] + b0, 0.f);
            float v10 = fmaxf(acc[mt][nt][2] + b1, 0.f);
            float v11 = fmaxf(acc[mt][nt][3] + b1, 0.f);
            if (TRANSOUT) {
                Cout[((size_t)b*Ln + col    )*DIMn + r0    ] = v00;
                Cout[((size_t)b*Ln + col + 1)*DIMn + r0    ] = v01;
                Cout[((size_t)b*Ln + col    )*DIMn + r0 + 8] = v10;
                Cout[((size_t)b*Ln + col + 1)*DIMn + r0 + 8] = v11;
            } else {
                Cout[((size_t)b*256 + r0    )*LP + 1 + col    ] = v00;
                Cout[((size_t)b*256 + r0    )*LP + 1 + col + 1] = v01;
                Cout[((size_t)b*256 + r0 + 8)*LP + 1 + col    ] = v10;
                Cout[((size_t)b*256 + r0 + 8)*LP + 1 + col + 1] = v11;
            }
        }
    }
}

// ---------------- row stats / mean pool: warp per row ----------------
__global__ void rowstat_kernel(const float* __restrict__ x, float* __restrict__ mean,
                               float* __restrict__ rstd)
{
    int row = blockIdx.x*8 + (threadIdx.x >> 5);
    int lane = threadIdx.x & 31;
    const float* xr = x + (size_t)row*DIMn + lane*8;
    float4 a = *(const float4*)xr;
    float4 c = *(const float4*)(xr + 4);
    float sum = a.x+a.y+a.z+a.w + c.x+c.y+c.z+c.w;
    #pragma unroll
    for (int off = 16; off > 0; off >>= 1) sum += __shfl_xor_sync(0xffffffffu, sum, off);
    float m = sum * (1.f/DIMn);
    float d0=a.x-m, d1=a.y-m, d2=a.z-m, d3=a.w-m;
    float d4=c.x-m, d5=c.y-m, d6=c.z-m, d7=c.w-m;
    float sq = d0*d0+d1*d1+d2*d2+d3*d3+d4*d4+d5*d5+d6*d6+d7*d7;
    #pragma unroll
    for (int off = 16; off > 0; off >>= 1) sq += __shfl_xor_sync(0xffffffffu, sq, off);
    if (lane == 0) {
        mean[row] = m;
        rstd[row] = rsqrtf(sq * (1.f/DIMn) + 1e-5f);
    }
}

__global__ void meanpool_kernel(const float* __restrict__ x, float* __restrict__ w)
{
    int row = blockIdx.x*8 + (threadIdx.x >> 5);
    int lane = threadIdx.x & 31;
    const float* xr = x + (size_t)row*DIMn + lane*8;
    float4 a = *(const float4*)xr;
    float4 c = *(const float4*)(xr + 4);
    float sum = a.x+a.y+a.z+a.w + c.x+c.y+c.z+c.w;
    #pragma unroll
    for (int off = 16; off > 0; off >>= 1) sum += __shfl_xor_sync(0xffffffffu, sum, off);
    if (lane == 0) w[row] = sum * (1.f/DIMn);
}

// ---------------- 2xtf32 GEMM, software-pipelined, optional fused layernorm on A --------
template<int BM, bool GELU, bool HASB, bool HASR, bool LNA>
__global__ __launch_bounds__(256)
void gemm_tf32_kernel(const float* __restrict__ A, const float* __restrict__ Bm,
                      const float* __restrict__ bias, const float* __restrict__ resid,
                      float* __restrict__ C, int M, int N, int K,
                      const float* __restrict__ lnm, const float* __restrict__ lnr,
                      const float* __restrict__ lns, const float* __restrict__ lnb)
{
    constexpr int WM  = BM/32;
    constexpr int WN  = 8/WM;
    constexpr int WTN = 128/WN;
    constexpr int NT  = WTN/8;
    constexpr int AV  = BM/32;
    constexpr int BUFU = 2*BM*36 + 32*132;
    extern __shared__ unsigned smu[];

    int tid = threadIdx.x;
    int warp = tid >> 5, lane = tid & 31;
    int g = lane >> 2, t = lane & 3;
    int wm = warp % WM, wn = warp / WM;
    int bm = blockIdx.y * BM, bn = blockIdx.x * 128;

    float acc[2][NT][4];
    #pragma unroll
    for (int mt = 0; mt < 2; mt++)
        #pragma unroll
        for (int nt = 0; nt < NT; nt++)
            #pragma unroll
            for (int i = 0; i < 4; i++) acc[mt][nt][i] = 0.f;

    float4 pa[AV], pb[4];
    float pm[AV], pr[AV];

    if (LNA) {
        #pragma unroll
        for (int v = 0; v < AV; v++) {
            int slot = tid + 256*v;
            int r = slot >> 3;
            pm[v] = lnm[bm + r];
            pr[v] = lnr[bm + r];
        }
    }

    auto LDG_TILE = [&](int k0) {
        #pragma unroll
        for (int v = 0; v < AV; v++) {
            int slot = tid + 256*v;
            int r = slot >> 3, c4 = (slot & 7) * 4;
            pa[v] = *(const float4*)&A[(size_t)(bm + r)*K + k0 + c4];
        }
        #pragma unroll
        for (int v = 0; v < 4; v++) {
            int slot = tid + 256*v;
            int kr = slot >> 5, c4 = (slot & 31) * 4;
            pb[v] = *(const float4*)&Bm[(size_t)(k0 + kr)*N + bn + c4];
        }
    };
    auto STS_TILE = [&](int buf, int k0) {
        unsigned* Ah = smu + buf*BUFU;
        unsigned* Al = Ah + BM*36;
        unsigned* Bs = Ah + 2*BM*36;
        #pragma unroll
        for (int v = 0; v < AV; v++) {
            int slot = tid + 256*v;
            int r = slot >> 3, c4 = (slot & 7) * 4;
            float4 av = pa[v];
            if (LNA) {
                float4 s4 = *(const float4*)&lns[k0 + c4];
                float4 b4 = *(const float4*)&lnb[k0 + c4];
                float mm = pm[v], rs = pr[v];
                av.x = (av.x - mm)*rs*s4.x + b4.x;
                av.y = (av.y - mm)*rs*s4.y + b4.y;
                av.z = (av.z - mm)*rs*s4.z + b4.z;
                av.w = (av.w - mm)*rs*s4.w + b4.w;
            }
            unsigned h0 = tf32_of(av.x), h1 = tf32_of(av.y), h2 = tf32_of(av.z), h3 = tf32_of(av.w);
            *(uint4*)&Ah[r*36 + c4] = make_uint4(h0, h1, h2, h3);
            *(uint4*)&Al[r*36 + c4] = make_uint4(
                tf32_of(av.x - __uint_as_float(h0)), tf32_of(av.y - __uint_as_float(h1)),
                tf32_of(av.z - __uint_as_float(h2)), tf32_of(av.w - __uint_as_float(h3)));
        }
        #pragma unroll
        for (int v = 0; v < 4; v++) {
            int slot = tid + 256*v;
            int kr = slot >> 5, c4 = (slot & 31) * 4;
            *(uint4*)&Bs[kr*132 + c4] = make_uint4(tf32_of(pb[v].x), tf32_of(pb[v].y),
                                                   tf32_of(pb[v].z), tf32_of(pb[v].w));
        }
    };

    int nT = K / 32;
    LDG_TILE(0);
    STS_TILE(0, 0);
    int cur = 0;
    for (int tt = 0; tt < nT; tt++) {
        if (tt + 1 < nT) LDG_TILE((tt+1)*32);
        __syncthreads();
        unsigned* Ah = smu + cur*BUFU;
        unsigned* Al = Ah + BM*36;
        unsigned* Bs = Ah + 2*BM*36;
        #pragma unroll
        for (int kk = 0; kk < 4; kk++) {
            int kb = kk * 8;
            unsigned ah[2][4], al[2][4];
            #pragma unroll
            for (int mt = 0; mt < 2; mt++) {
                int m = wm*32 + mt*16;
                ah[mt][0] = Ah[(m + g    )*36 + kb + t    ];
                ah[mt][1] = Ah[(m + g + 8)*36 + kb + t    ];
                ah[mt][2] = Ah[(m + g    )*36 + kb + t + 4];
                ah[mt][3] = Ah[(m + g + 8)*36 + kb + t + 4];
                al[mt][0] = Al[(m + g    )*36 + kb + t    ];
                al[mt][1] = Al[(m + g + 8)*36 + kb + t    ];
                al[mt][2] = Al[(m + g    )*36 + kb + t + 4];
                al[mt][3] = Al[(m + g + 8)*36 + kb + t + 4];
            }
            #pragma unroll
            for (int nt = 0; nt < NT; nt++) {
                int n = wn*WTN + nt*8 + g;
                unsigned bh[2];
                bh[0] = Bs[(kb + t    )*132 + n];
                bh[1] = Bs[(kb + t + 4)*132 + n];
                #pragma unroll
                for (int mt = 0; mt < 2; mt++) {
                    mma_tf32(acc[mt][nt], al[mt], bh);   // lo*hi
                    mma_tf32(acc[mt][nt], ah[mt], bh);   // hi*hi
                }
            }
        }
        if (tt + 1 < nT) STS_TILE(cur ^ 1, (tt+1)*32);
        cur ^= 1;
    }
    #pragma unroll
    for (int mt = 0; mt < 2; mt++) {
        int r0 = bm + wm*32 + mt*16 + g;
        #pragma unroll
        for (int nt = 0; nt < NT; nt++) {
            int col = bn + wn*WTN + nt*8 + 2*t;
            float2 v0 = make_float2(acc[mt][nt][0], acc[mt][nt][1]);
            float2 v1 = make_float2(acc[mt][nt][2], acc[mt][nt][3]);
            if (HASB) {
                float2 bb = *(const float2*)&bias[col];
                v0.x += bb.x; v0.y += bb.y; v1.x += bb.x; v1.y += bb.y;
            }
            if (GELU) {
                v0.x = 0.5f*v0.x*(1.f + erff(v0.x*0.70710678118f));
                v0.y = 0.5f*v0.y*(1.f + erff(v0.y*0.70710678118f));
                v1.x = 0.5f*v1.x*(1.f + erff(v1.x*0.70710678118f));
                v1.y = 0.5f*v1.y*(1.f + erff(v1.y*0.70710678118f));
            }
            if (HASR) {
                float2 r0v = *(const float2*)&resid[(size_t)r0*N + col];
                float2 r1v = *(const float2*)&resid[(size_t)(r0+8)*N + col];
                v0.x += r0v.x; v0.y += r0v.y; v1.x += r1v.x; v1.y += r1v.y;
            }
            *(float2*)&C[(size_t)r0*N + col]     = v0;
            *(float2*)&C[(size_t)(r0+8)*N + col] = v1;
        }
    }
}

// ---------------- flash attention (tf32 mma), 64 q-rows / 128 threads ----------------
// K/V double-buffered: LDG for tile jt+1 issued before compute of jt, STS after.
__global__ __launch_bounds__(128, 2)
void attn_kernel(const float* __restrict__ qkv, const float* __restrict__ pos,
                 float* __restrict__ out)
{
    extern __shared__ unsigned smu[];
    unsigned* Qs  = smu;                 // [64][68]
    unsigned* Ps  = smu + 64*68;         // [64][68]
    unsigned* KVb = smu + 2*64*68;       // 2 bufs x (Ks[64][68] + Vs[64][68])

    int bq = blockIdx.x, h = blockIdx.y, b = blockIdx.z;
    int i0 = bq * 64;
    int tid = threadIdx.x;
    int warp = tid >> 5, lane = tid & 31;
    int g = lane >> 2, t = lane & 3;
    int m0 = warp * 16;
    const float* base = qkv + (size_t)b * Ln * QKV3n;

    // load Q tile [64][64] -> tf32
    #pragma unroll
    for (int v = 0; v < 8; v++) {
        int f = tid + 128*v;
        int r = f >> 4, c4 = (f & 15) * 4;
        float4 qv = *(const float4*)&base[(size_t)(i0 + r)*QKV3n + h*64 + c4];
        *(uint4*)&Qs[r*68 + c4] = make_uint4(tf32_of(qv.x), tf32_of(qv.y), tf32_of(qv.z), tf32_of(qv.w));
    }

    float4 pk[8], pv[8];
    auto LDG_KV = [&](int j0) {
        #pragma unroll
        for (int v = 0; v < 8; v++) {
            int f = tid + 128*v;
            int r = f >> 4, c4 = (f & 15) * 4;
            pk[v] = *(const float4*)&base[(size_t)(j0 + r)*QKV3n + INNERn   + h*64 + c4];
            pv[v] = *(const float4*)&base[(size_t)(j0 + r)*QKV3n + 2*INNERn + h*64 + c4];
        }
    };
    auto STS_KV = [&](int buf) {
        unsigned* Ks = KVb + buf*2*64*68;
        unsigned* Vs = Ks + 64*68;
        #pragma unroll
        for (int v = 0; v < 8; v++) {
            int f = tid + 128*v;
            int r = f >> 4, c4 = (f & 15) * 4;
            *(uint4*)&Ks[r*68 + c4] = make_uint4(tf32_of(pk[v].x), tf32_of(pk[v].y),
                                                 tf32_of(pk[v].z), tf32_of(pk[v].w));
            *(uint4*)&Vs[r*68 + c4] = make_uint4(tf32_of(pv[v].x), tf32_of(pv[v].y),
                                                 tf32_of(pv[v].z), tf32_of(pv[v].w));
        }
    };

    float o[8][4];
    #pragma unroll
    for (int nt = 0; nt < 8; nt++)
        #pragma unroll
        for (int i = 0; i < 4; i++) o[nt][i] = 0.f;
    float mrow0 = -1e30f, mrow1 = -1e30f, lrow0 = 0.f, lrow1 = 0.f;

    const float* pr0 = pos + ((size_t)(h*Ln + i0 + m0 + g    ))*Ln;
    const float* pr1 = pos + ((size_t)(h*Ln + i0 + m0 + g + 8))*Ln;

    LDG_KV(0);
    STS_KV(0);
    int cur = 0;
    for (int jt = 0; jt < 16; jt++) {
        int j0 = jt * 64;
        if (jt + 1 < 16) LDG_KV((jt+1)*64);
        __syncthreads();   // STS of buf[cur] complete; prior reads of buf[cur^1] done
        unsigned* Ks = KVb + cur*2*64*68;
        unsigned* Vs = Ks + 64*68;

        // S = Q @ K^T : warp band m0..m0+15, cols 0..63
        float sa[8][4];
        #pragma unroll
        for (int nt = 0; nt < 8; nt++)
            #pragma unroll
            for (int i = 0; i < 4; i++) sa[nt][i] = 0.f;
        #pragma unroll
        for (int kc = 0; kc < 8; kc++) {
            int kb = kc * 8;
            unsigned a[4];
            a[0] = Qs[(m0 + g    )*68 + kb + t    ];
            a[1] = Qs[(m0 + g + 8)*68 + kb + t    ];
            a[2] = Qs[(m0 + g    )*68 + kb + t + 4];
            a[3] = Qs[(m0 + g + 8)*68 + kb + t + 4];
            #pragma unroll
            for (int nt = 0; nt < 8; nt++) {
                int n = nt*8 + g;
                unsigned bb[2];
                bb[0] = Ks[n*68 + kb + t    ];   // B[k][n] = K[n][k]
                bb[1] = Ks[n*68 + kb + t + 4];
                mma_tf32(sa[nt], a, bb);
            }
        }
        // scale + pos bias
        #pragma unroll
        for (int nt = 0; nt < 8; nt++) {
            float2 p0 = *(const float2*)&pr0[j0 + nt*8 + 2*t];
            float2 p1 = *(const float2*)&pr1[j0 + nt*8 + 2*t];
            sa[nt][0] = sa[nt][0]*0.125f + p0.x;
            sa[nt][1] = sa[nt][1]*0.125f + p0.y;
            sa[nt][2] = sa[nt][2]*0.125f + p1.x;
            sa[nt][3] = sa[nt][3]*0.125f + p1.y;
        }
        float mx0 = -1e30f, mx1 = -1e30f;
        #pragma unroll
        for (int nt = 0; nt < 8; nt++) {
            mx0 = fmaxf(mx0, fmaxf(sa[nt][0], sa[nt][1]));
            mx1 = fmaxf(mx1, fmaxf(sa[nt][2], sa[nt][3]));
        }
        mx0 = fmaxf(mx0, __shfl_xor_sync(0xffffffffu, mx0, 1));
        mx0 = fmaxf(mx0, __shfl_xor_sync(0xffffffffu, mx0, 2));
        mx1 = fmaxf(mx1, __shfl_xor_sync(0xffffffffu, mx1, 1));
        mx1 = fmaxf(mx1, __shfl_xor_sync(0xffffffffu, mx1, 2));
        float mn0 = fmaxf(mrow0, mx0), mn1 = fmaxf(mrow1, mx1);
        float corr0 = __expf(mrow0 - mn0), corr1 = __expf(mrow1 - mn1);
        float ts0 = 0.f, ts1 = 0.f;
        #pragma unroll
        for (int nt = 0; nt < 8; nt++) {
            float e0 = __expf(sa[nt][0] - mn0);
            float e1 = __expf(sa[nt][1] - mn0);
            float e2 = __expf(sa[nt][2] - mn1);
            float e3 = __expf(sa[nt][3] - mn1);
            ts0 += e0 + e1; ts1 += e2 + e3;
            int c = nt*8 + 2*t;
            *(uint2*)&Ps[(m0 + g    )*68 + c] = make_uint2(tf32_of(e0), tf32_of(e1));
            *(uint2*)&Ps[(m0 + g + 8)*68 + c] = make_uint2(tf32_of(e2), tf32_of(e3));
        }
        ts0 += __shfl_xor_sync(0xffffffffu, ts0, 1);
        ts0 += __shfl_xor_sync(0xffffffffu, ts0, 2);
        ts1 += __shfl_xor_sync(0xffffffffu, ts1, 1);
        ts1 += __shfl_xor_sync(0xffffffffu, ts1, 2);
        lrow0 = lrow0*corr0 + ts0;
        lrow1 = lrow1*corr1 + ts1;
        mrow0 = mn0; mrow1 = mn1;
        #pragma unroll
        for (int nt = 0; nt < 8; nt++) {
            o[nt][0] *= corr0; o[nt][1] *= corr0;
            o[nt][2] *= corr1; o[nt][3] *= corr1;
        }
        __syncwarp();
        // O += P @ V
        #pragma unroll
        for (int kc = 0; kc < 8; kc++) {
            int kb = kc * 8;
            unsigned a[4];
            a[0] = Ps[(m0 + g    )*68 + kb + t    ];
            a[1] = Ps[(m0 + g + 8)*68 + kb + t    ];
            a[2] = Ps[(m0 + g    )*68 + kb + t + 4];
            a[3] = Ps[(m0 + g + 8)*68 + kb + t + 4];
            #pragma unroll
            for (int nt = 0; nt < 8; nt++) {
                unsigned bb[2];
                bb[0] = Vs[(kb + t    )*68 + nt*8 + g];
                bb[1] = Vs[(kb + t + 4)*68 + nt*8 + g];
                mma_tf32(o[nt], a, bb);
            }
        }
        if (jt + 1 < 16) STS_KV(cur ^ 1);
        cur ^= 1;
    }
    float inv0 = 1.f / lrow0, inv1 = 1.f / lrow1;
    size_t r0 = (size_t)b*Ln + i0 + m0 + g;
    size_t r1 = r0 + 8;
    #pragma unroll
    for (int nt = 0; nt < 8; nt++) {
        int col = h*64 + nt*8 + 2*t;
        *(float2*)&out[r0*INNERn + col] = make_float2(o[nt][0]*inv0, o[nt][1]*inv0);
        *(float2*)&out[r1*INNERn + col] = make_float2(o[nt][2]*inv1, o[nt][3]*inv1);
    }
}

// ---------------- SE pool tail ----------------
__global__ void se1_kernel(const float* __restrict__ wv, const float* __restrict__ w1,
                           const float* __restrict__ b1, float* __restrict__ t)
{
    int tid = threadIdx.x;                            // 512
    int b = tid >> 7, j = tid & 127;
    float acc = b1[j];
    for (int l = 0; l < Ln; l++) acc += wv[b*Ln + l] * w1[l*128 + j];
    t[tid] = fmaxf(acc, 0.f);
}

__global__ void se2_kernel(const float* __restrict__ t, const float* __restrict__ w2,
                           const float* __restrict__ b2, float* __restrict__ u)
{
    int idx = blockIdx.x * 256 + threadIdx.x;         // 4096
    int b = idx >> 10, l = idx & (Ln-1);
    float acc = b2[l];
    #pragma unroll
    for (int j = 0; j < 128; j++) acc += t[b*128 + j] * w2[j*Ln + l];
    u[idx] = 1.f / (1.f + __expf(-acc));
}

__global__ void pool_out_kernel(const float* __restrict__ u, const float* __restrict__ x,
                                float* __restrict__ out)
{
    int b = blockIdx.x, d = threadIdx.x;              // 4 x 256
    float acc = 0.f;
    for (int l = 0; l < Ln; l++) acc += u[b*Ln + l] * x[((size_t)b*Ln + l)*DIMn + d];
    out[b*DIMn + d] = acc;
}

// ---------------- host launch ----------------
extern "C" void kernel_launch(void* const* d_in, const int* in_sizes, int n_in,
                              void* d_out, int out_size)
{
    const float* img     = (const float*)d_in[0];
    const float* conv1_w = (const float*)d_in[1];
    const float* conv1_b = (const float*)d_in[2];
    const float* conv2_w = (const float*)d_in[3];
    const float* conv2_b = (const float*)d_in[4];
    const float* conv3_w = (const float*)d_in[5];
    const float* conv3_b = (const float*)d_in[6];
    const float* ln1_s   = (const float*)d_in[7];
    const float* ln1_b   = (const float*)d_in[8];
    const float* qkv_w   = (const float*)d_in[9];
    const float* pos     = (const float*)d_in[10];
    const float* out_w   = (const float*)d_in[11];
    const float* out_b   = (const float*)d_in[12];
    const float* ln2_s   = (const float*)d_in[13];
    const float* ln2_b   = (const float*)d_in[14];
    const float* ff_w1   = (const float*)d_in[15];
    const float* ff_b1   = (const float*)d_in[16];
    const float* ff_w2   = (const float*)d_in[17];
    const float* ff_b2   = (const float*)d_in[18];
    const float* se_w1   = (const float*)d_in[19];
    const float* se_b1   = (const float*)d_in[20];
    const float* se_w2   = (const float*)d_in[21];
    const float* se_b2   = (const float*)d_in[22];
    float* out = (float*)d_out;

    float *c1p, *c2p, *w2t, *w3t, *x, *qkv, *att, *mlp, *mstat, *rstat, *pw, *t, *u;
    cudaGetSymbolAddress((void**)&c1p, g_c1p);
    cudaGetSymbolAddress((void**)&c2p, g_c2p);
    cudaGetSymbolAddress((void**)&w2t, g_w2t);
    cudaGetSymbolAddress((void**)&w3t, g_w3t);
    cudaGetSymbolAddress((void**)&x,   g_x);
    cudaGetSymbolAddress((void**)&qkv, g_qkv);
    cudaGetSymbolAddress((void**)&att, g_att);
    cudaGetSymbolAddress((void**)&mlp, g_mlp);
    cudaGetSymbolAddress((void**)&mstat, g_m);
    cudaGetSymbolAddress((void**)&rstat, g_r);
    cudaGetSymbolAddress((void**)&pw,  g_pw);
    cudaGetSymbolAddress((void**)&t,   g_t);
    cudaGetSymbolAddress((void**)&u,   g_u);

    const int ATTN_SMEM = 6 * 64 * 68 * 4;                     // 104448 B (Q + P + 2x(K+V))
    const int GEMM_SMEM_128 = 2*(2*128*36 + 32*132) * 4;       // 107520 B
    const int GEMM_SMEM_64  = 2*(2*64*36  + 32*132) * 4;       // 70656 B
    cudaFuncSetAttribute(attn_kernel, cudaFuncAttributeMaxDynamicSharedMemorySize, ATTN_SMEM);
    cudaFuncSetAttribute(gemm_tf32_kernel<128,false,false,false,true>,
                         cudaFuncAttributeMaxDynamicSharedMemorySize, GEMM_SMEM_128);
    cudaFuncSetAttribute(gemm_tf32_kernel<128,true,true,false,true>,
                         cudaFuncAttributeMaxDynamicSharedMemorySize, GEMM_SMEM_128);
    cudaFuncSetAttribute(gemm_tf32_kernel<64,false,true,true,false>,
                         cudaFuncAttributeMaxDynamicSharedMemorySize, GEMM_SMEM_64);
    cudaFuncSetAttribute(conv_gemm_kernel<false>,
                         cudaFuncAttributeMaxDynamicSharedMemorySize, GEMM_SMEM_64);
    cudaFuncSetAttribute(conv_gemm_kernel<true>,
                         cudaFuncAttributeMaxDynamicSharedMemorySize, GEMM_SMEM_64);

    // conv patch embed
    conv1_kernel<<<(Bn*256*2*Ln + 255)/256, 256>>>(img, conv1_w, conv1_b, c1p);
    pad_zero_kernel<<<(2048*8 + 1024*8 + 255)/256, 256>>>(c1p, c2p);
    wtrans_kernel<<<(256*1536 + 255)/256, 256>>>(conv2_w, w2t, 512, 256*1536);
    wtrans_kernel<<<(256*768  + 255)/256, 256>>>(conv3_w, w3t, 256, 256*768);
    conv_gemm_kernel<false><<<dim3(8, 4, Bn), 256, GEMM_SMEM_64>>>(w2t, c1p, conv2_b, c2p, 1536, 512, 9);
    conv_gemm_kernel<true ><<<dim3(8, 4, Bn), 256, GEMM_SMEM_64>>>(w3t, c2p, conv3_b, x,   768,  256, 8);

    for (int lyr = 0; lyr < DEPTHn; lyr++) {
        // attention block (LN fused into qkv A-staging)
        rowstat_kernel<<<ROWS/8, 256>>>(x, mstat, rstat);
        gemm_tf32_kernel<128,false,false,false,true><<<dim3(QKV3n/128, ROWS/128), 256, GEMM_SMEM_128>>>(
            x, qkv_w + (size_t)lyr*DIMn*QKV3n, nullptr, nullptr, qkv, ROWS, QKV3n, DIMn,
            mstat, rstat, ln1_s + lyr*DIMn, ln1_b + lyr*DIMn);
        attn_kernel<<<dim3(Ln/64, HEADSn, Bn), 128, ATTN_SMEM>>>(
            qkv, pos + (size_t)lyr*HEADSn*Ln*Ln, att);
        gemm_tf32_kernel<64,false,true,true,false><<<dim3(DIMn/128, ROWS/64), 256, GEMM_SMEM_64>>>(
            att, out_w + (size_t)lyr*INNERn*DIMn, out_b + lyr*DIMn, x, x, ROWS, DIMn, INNERn,
            nullptr, nullptr, nullptr, nullptr);
        // MLP block (LN fused into ff1 A-staging)
        rowstat_kernel<<<ROWS/8, 256>>>(x, mstat, rstat);
        gemm_tf32_kernel<128,true,true,false,true><<<dim3(MLPn/128, ROWS/128), 256, GEMM_SMEM_128>>>(
            x, ff_w1 + (size_t)lyr*DIMn*MLPn, ff_b1 + lyr*MLPn, nullptr, mlp, ROWS, MLPn, DIMn,
            mstat, rstat, ln2_s + lyr*DIMn, ln2_b + lyr*DIMn);
        gemm_tf32_kernel<64,false,true,true,false><<<dim3(DIMn/128, ROWS/64), 256, GEMM_SMEM_64>>>(
            mlp, ff_w2 + (size_t)lyr*MLPn*DIMn, ff_b2 + lyr*DIMn, x, x, ROWS, DIMn, MLPn,
            nullptr, nullptr, nullptr, nullptr);
    }

    // SE attention pool
    meanpool_kernel<<<ROWS/8, 256>>>(x, pw);
    se1_kernel<<<1, 512>>>(pw, se_w1, se_b1, t);
    se2_kernel<<<(Bn*Ln)/256, 256>>>(t, se_w2, se_b2, u);
    pool_out_kernel<<<Bn, 256>>>(u, x, out);
}